// round 13
// baseline (speedup 1.0000x reference)
#include <cuda_runtime.h>
#include <cstdint>
#include <math.h>

#define B_   32
#define S_   384
#define T_   (B_*S_)     // 12288
#define H_   600
#define IN_  303
#define G3_  1800
#define NCD  30          // CTAs per direction (frozen)
#define UPC  20          // hidden units per CTA (1 warp each)
#define SCAN_THREADS 640 // 20 warps

// gemm tiling inside merged kernel
#define TM 128
#define TN 64
#define TK 16
#define MT_TILES (T_ / TM)                 // 96 m-tiles (3 per batch)
#define NT_TILES ((G3_ + TN - 1) / TN)     // 29 n-tiles
#define TILES_PER_BATCH (3 * NT_TILES)     // 87

// ---------------- device scratch (static allocation only) ----------------
__device__ float g_G[(size_t)T_ * G3_];     // input projections, 88.5 MB
__device__ float g_fst[(size_t)T_ * H_];    // forward hidden states
__device__ float g_bst[(size_t)T_ * H_];    // backward hidden states
// self-synchronizing h exchange: (tag<<32)|bits(h), [phase][dir][unit]
__device__ __align__(16) unsigned long long g_hx[2][2][640];
__device__ int   g_done[B_];                // per-batch gemm-tile completion counters
__device__ float g_hs[B_][1200];
__device__ float g_q[B_][1200];
__device__ float g_scores[B_][S_];
__device__ float g_cat[B_][2400];
__device__ float g_gated[B_][1200];

// ---------------- helpers ----------------
__device__ __forceinline__ void cp_async4(void* smem, const void* gmem) {
    uint32_t s = (uint32_t)__cvta_generic_to_shared(smem);
    asm volatile("cp.async.ca.shared.global [%0], [%1], 4;\n" :: "r"(s), "l"(gmem));
}
__device__ __forceinline__ void cp_commit() { asm volatile("cp.async.commit_group;\n"); }
__device__ __forceinline__ void cp_wait3()  { asm volatile("cp.async.wait_group 3;\n"); }

// 16B poll: two adjacent (tag|h) pairs; each aligned 8B half individually atomic
__device__ __forceinline__ void ld_pair2(const unsigned long long* p,
                                         unsigned long long& a, unsigned long long& b) {
    asm volatile("ld.volatile.global.v2.u64 {%0,%1}, [%2];" : "=l"(a), "=l"(b) : "l"(p));
}
__device__ __forceinline__ void st_pair(unsigned long long* p, unsigned long long v) {
    asm volatile("st.relaxed.gpu.global.b64 [%0], %1;" :: "l"(p), "l"(v));
}
__device__ __forceinline__ int ld_acquire_s32(const int* p) {
    int v;
    asm volatile("ld.acquire.gpu.global.s32 %0, [%1];" : "=r"(v) : "l"(p));
    return v;
}
__device__ __forceinline__ void red_release_add(int* p, int v) {
    asm volatile("red.release.gpu.global.add.s32 [%0], %1;" :: "l"(p), "r"(v));
}
__device__ __forceinline__ void ffma2(unsigned long long& d, unsigned long long a,
                                      unsigned long long b, unsigned long long c) {
    asm("fma.rn.f32x2 %0, %1, %2, %3;" : "=l"(d) : "l"(a), "l"(b), "l"(c));
}

__device__ __forceinline__ float fast_tanh(float x) {
    float y;
    asm("tanh.approx.f32 %0, %1;" : "=f"(y) : "f"(x));
    return y;
}
__device__ __forceinline__ float fast_sigmoid(float x) {
    return 0.5f * fast_tanh(0.5f * x) + 0.5f;
}
__device__ __forceinline__ float sigmoidf_(float x) { return 1.f / (1.f + expf(-x)); }

__device__ __forceinline__ int grow_for(int dir, int t) {
    if (dir == 0) return t;
    int b = t / S_, s = t - b * S_;
    return b * S_ + (S_ - 1 - s);
}

// ---------------- init: reset exchange state each launch ----------------
__global__ void k_init() {
    int i = blockIdx.x * blockDim.x + threadIdx.x;
    if (i < 2 * 2 * 640) ((unsigned long long*)g_hx)[i] = 0ull;  // h=0, tag=0
    if (i < B_) g_done[i] = 0;
}

// ============ merged persistent kernel: scan (blocks 0..59) + gemm (60..) ============
__global__ __launch_bounds__(SCAN_THREADS, 1)
void fused_kernel(const float* __restrict__ Whh, const float* __restrict__ bhh,
                  const float* __restrict__ ctx, const int* __restrict__ tags,
                  const float* __restrict__ bio, const float* __restrict__ Wih,
                  const float* __restrict__ bih) {
    const int tid = threadIdx.x;

    if (blockIdx.x >= 2 * NCD) {
        // ---------------- gemm path: one 128x64 tile of G = emb @ Wih.T + bih ----------
        __shared__ float As[TK][TM + 4];
        __shared__ float Bs[TK][TN + 4];
        const int gb = blockIdx.x - 2 * NCD;
        const int mt = gb / NT_TILES;
        const int nt = gb % NT_TILES;
        const int m0 = mt * TM;
        const int n0 = nt * TN;
        const bool act = tid < 256;           // 256 worker threads; all 640 hit barriers
        const int tx = tid & 15, ty = tid >> 4;

        float acc[8][4];
        #pragma unroll
        for (int i = 0; i < 8; i++)
            #pragma unroll
            for (int j = 0; j < 4; j++) acc[i][j] = 0.f;

        for (int k0 = 0; k0 < IN_; k0 += TK) {
            if (act) {
                #pragma unroll
                for (int i = 0; i < 8; i++) {
                    int am = ty + i * 16;
                    int k = k0 + tx;
                    int t = m0 + am;
                    float v = 0.f;
                    if (k < IN_) {
                        if (k < 3) v = bio[tags[t] * 3 + k];
                        else       v = ctx[(size_t)t * 300 + (k - 3)];
                    }
                    As[tx][am] = v;
                }
                #pragma unroll
                for (int i = 0; i < 4; i++) {
                    int bn = ty + i * 16;
                    int j = n0 + bn;
                    int k = k0 + tx;
                    float v = 0.f;
                    if (j < G3_ && k < IN_) v = Wih[(size_t)j * IN_ + k];
                    Bs[tx][bn] = v;
                }
            }
            __syncthreads();
            if (act) {
                #pragma unroll
                for (int kk = 0; kk < TK; kk++) {
                    float a[8], b[4];
                    #pragma unroll
                    for (int i = 0; i < 8; i++) a[i] = As[kk][ty * 8 + i];
                    #pragma unroll
                    for (int j = 0; j < 4; j++) b[j] = Bs[kk][tx * 4 + j];
                    #pragma unroll
                    for (int i = 0; i < 8; i++)
                        #pragma unroll
                        for (int j = 0; j < 4; j++) acc[i][j] = fmaf(a[i], b[j], acc[i][j]);
                }
            }
            __syncthreads();
        }
        if (act) {
            #pragma unroll
            for (int i = 0; i < 8; i++) {
                int t = m0 + ty * 8 + i;
                #pragma unroll
                for (int j = 0; j < 4; j++) {
                    int jj = n0 + tx * 4 + j;
                    if (jj < G3_) g_G[(size_t)t * G3_ + jj] = acc[i][j] + bih[jj];
                }
            }
        }
        __syncthreads();
        if (tid == 0) red_release_add(&g_done[mt / 3], 1);  // publish tile (release)
        return;
    }

    // ---------------- scan path (frozen protocol; dual-phase poll chains) ------------
    const int w    = tid >> 5;
    const int lane = tid & 31;
    const int dir  = blockIdx.x / NCD;
    const int c    = blockIdx.x % NCD;
    const int u0   = c * UPC;
    const int u    = u0 + w;        // hidden unit handled by this warp

    __shared__ __align__(16) float sh_h[648];
    __shared__ float sh_gi[8][64];  // 8 slots so prefetch never writes a live slot

    // W_hh rows packed as f32x2 pairs
    unsigned long long Wr2[10], Wz2[10], Wn2[10];
    #pragma unroll
    for (int m = 0; m < 10; m++) {
        int c0 = 64 * m + 2 * lane;
        float r0 = (c0     < H_) ? Whh[(size_t)u * H_ + c0]              : 0.f;
        float r1 = (c0 + 1 < H_) ? Whh[(size_t)u * H_ + c0 + 1]          : 0.f;
        float z0 = (c0     < H_) ? Whh[(size_t)(600 + u) * H_ + c0]      : 0.f;
        float z1 = (c0 + 1 < H_) ? Whh[(size_t)(600 + u) * H_ + c0 + 1]  : 0.f;
        float n0 = (c0     < H_) ? Whh[(size_t)(1200 + u) * H_ + c0]     : 0.f;
        float n1 = (c0 + 1 < H_) ? Whh[(size_t)(1200 + u) * H_ + c0 + 1] : 0.f;
        Wr2[m] = ((unsigned long long)__float_as_uint(r1) << 32) | __float_as_uint(r0);
        Wz2[m] = ((unsigned long long)__float_as_uint(z1) << 32) | __float_as_uint(z0);
        Wn2[m] = ((unsigned long long)__float_as_uint(n1) << 32) | __float_as_uint(n0);
    }
    const float bhr = bhh[u], bhz = bhh[600 + u], bhn = bhh[1200 + u];

    if (tid < 48) sh_h[600 + tid] = 0.f;   // zero pad cols 600..647 (W pad is 0)

    int rb = -1;   // last batch confirmed ready (prefetch threads only)

    // prologue: prefetch gi for steps 0..3 (batch 0; gate on its readiness)
    for (int tp = 0; tp < 4; tp++) {
        if (tid < 3 * UPC) {
            if (rb < 0) { while (ld_acquire_s32(&g_done[0]) < TILES_PER_BATCH) {} rb = 0; }
            int grow = grow_for(dir, tp);
            int col = (tid / UPC) * 600 + u0 + (tid % UPC);
            cp_async4(&sh_gi[tp][tid], &g_G[(size_t)grow * G3_ + col]);
        }
        cp_commit();
    }

    float* states = dir ? g_bst : g_fst;

    for (int t = 0; t < T_; t++) {
        // 300 threads, 2 units each, via dual phase-offset dependent poll chains:
        // chain A issues; ~190cy in-order-issue dummy chain; chain B issues.
        // Alternating check/reissue keeps the two chains sampling ~RTT/2 apart,
        // halving detection quantization at UNCHANGED in-flight poll count.
        if (tid < 300) {
            const unsigned long long* p = &g_hx[t & 1][dir][2 * tid];
            unsigned long long a0, a1, b0, b1;
            ld_pair2(p, a0, a1);                         // chain A sample
            float dly = (float)(t + 1);
            #pragma unroll
            for (int i = 0; i < 12; i++)                 // ~190cy issue delay (12 x MUFU lat16)
                asm volatile("rcp.approx.f32 %0, %0;" : "+f"(dly));
            ld_pair2(p, b0, b1);                         // chain B sample (phase-offset)
            const unsigned tt = (unsigned)t;
            unsigned long long r0, r1;
            while (true) {
                if ((unsigned)(a0 >> 32) == tt && (unsigned)(a1 >> 32) == tt) { r0 = a0; r1 = a1; break; }
                ld_pair2(p, a0, a1);
                if ((unsigned)(b0 >> 32) == tt && (unsigned)(b1 >> 32) == tt) { r0 = b0; r1 = b1; break; }
                ld_pair2(p, b0, b1);
            }
            sh_h[2 * tid]     = __uint_as_float((unsigned)r0);
            sh_h[2 * tid + 1] = __uint_as_float((unsigned)r1);
        }
        cp_wait3();          // gi for step t resident
        __syncthreads();

        // 3 dot products of length 600 via packed f32x2 FMA, W in registers
        unsigned long long ar2 = 0ull, az2 = 0ull, an2 = 0ull;
        #pragma unroll
        for (int m = 0; m < 10; m++) {
            unsigned long long h2 = *(const unsigned long long*)&sh_h[64 * m + 2 * lane];
            ffma2(ar2, Wr2[m], h2, ar2);
            ffma2(az2, Wz2[m], h2, az2);
            ffma2(an2, Wn2[m], h2, an2);
        }
        float ar = __uint_as_float((unsigned)ar2) + __uint_as_float((unsigned)(ar2 >> 32));
        float az = __uint_as_float((unsigned)az2) + __uint_as_float((unsigned)(az2 >> 32));
        float an = __uint_as_float((unsigned)an2) + __uint_as_float((unsigned)(an2 >> 32));
        #pragma unroll
        for (int off = 16; off; off >>= 1) {
            ar += __shfl_xor_sync(0xffffffffu, ar, off);
            az += __shfl_xor_sync(0xffffffffu, az, off);
            an += __shfl_xor_sync(0xffffffffu, an, off);
        }

        if (lane == 0) {
            float ir  = sh_gi[t & 7][w];
            float iz  = sh_gi[t & 7][UPC + w];
            float inn = sh_gi[t & 7][2 * UPC + w];
            float r = fast_sigmoid(ir + ar + bhr);
            float z = fast_sigmoid(iz + az + bhz);
            float n = fast_tanh(inn + r * (an + bhn));
            float hprev = sh_h[u];
            float hnew = (1.f - z) * n + z * hprev;
            unsigned long long pv =
                ((unsigned long long)(unsigned)(t + 1) << 32) |
                (unsigned long long)__float_as_uint(hnew);
            st_pair(&g_hx[(t + 1) & 1][dir][u], pv);   // publish first (critical path)
            states[(size_t)t * H_ + u] = hnew;
        }

        // prefetch gi for step t+4; gate on its batch being produced (32 polls total)
        int tp = t + 4;
        if (tp < T_ && tid < 3 * UPC) {
            int bb = tp / S_;
            if (bb != rb) { while (ld_acquire_s32(&g_done[bb]) < TILES_PER_BATCH) {} rb = bb; }
            int grow = grow_for(dir, tp);
            int col = (tid / UPC) * 600 + u0 + (tid % UPC);
            cp_async4(&sh_gi[tp & 7][tid], &g_G[(size_t)grow * G3_ + col]);
        }
        cp_commit();
        __syncthreads();     // confine polling to a short window; protect sh_h rewrite
    }
}

// ---------------- Phase 3 ----------------
__global__ void k_hs(float* __restrict__ out) {
    int b = blockIdx.x, j = threadIdx.x;  // block 600
    size_t tl = ((size_t)b * S_ + (S_ - 1)) * H_;
    g_hs[b][j]       = g_fst[tl + j];
    g_hs[b][600 + j] = g_bst[tl + j];
    if (b == 0) {   // final = concat(h_f, h_b)
        size_t te = ((size_t)T_ - 1) * H_;
        out[j]       = g_fst[te + j];
        out[600 + j] = g_bst[te + j];
    }
}

__global__ void k_q(const float* __restrict__ Wlin, const float* __restrict__ blin) {
    int wid = threadIdx.x >> 5, lane = threadIdx.x & 31;
    int j = blockIdx.x * 8 + wid;
    int b = blockIdx.y;
    const float* row = Wlin + (size_t)j * 1200;
    float s = 0.f;
    for (int k = lane; k < 1200; k += 32) s = fmaf(row[k], g_hs[b][k], s);
    #pragma unroll
    for (int off = 16; off; off >>= 1) s += __shfl_down_sync(0xffffffffu, s, off);
    if (lane == 0) g_q[b][j] = s + blin[j];
}

__global__ void k_sdot() {
    int wid = threadIdx.x >> 5, lane = threadIdx.x & 31;
    int s = blockIdx.x * 8 + wid;
    int b = blockIdx.y;
    size_t tl = ((size_t)b * S_ + s) * H_;
    float acc = 0.f;
    for (int k = lane; k < 600; k += 32) {
        acc = fmaf(g_q[b][k],       g_fst[tl + k], acc);
        acc = fmaf(g_q[b][600 + k], g_bst[tl + k], acc);
    }
    #pragma unroll
    for (int off = 16; off; off >>= 1) acc += __shfl_down_sync(0xffffffffu, acc, off);
    if (lane == 0) g_scores[b][s] = acc;
}

__global__ void k_softmax() {
    int b = blockIdx.x, s = threadIdx.x;   // block 384 = 12 warps
    __shared__ float sm[12];
    __shared__ float bc;
    float v = g_scores[b][s];
    float m = v;
    #pragma unroll
    for (int off = 16; off; off >>= 1) m = fmaxf(m, __shfl_xor_sync(0xffffffffu, m, off));
    if ((s & 31) == 0) sm[s >> 5] = m;
    __syncthreads();
    if (s == 0) {
        float mm = sm[0];
        for (int i = 1; i < 12; i++) mm = fmaxf(mm, sm[i]);
        bc = mm;
    }
    __syncthreads();
    float e = expf(v - bc);
    float t = e;
    #pragma unroll
    for (int off = 16; off; off >>= 1) t += __shfl_xor_sync(0xffffffffu, t, off);
    if ((s & 31) == 0) sm[s >> 5] = t;
    __syncthreads();
    if (s == 0) {
        float ss = 0.f;
        for (int i = 0; i < 12; i++) ss += sm[i];
        bc = ss;
    }
    __syncthreads();
    g_scores[b][s] = e / bc;
}

__global__ void k_ctx() {
    int b = blockIdx.x, j = threadIdx.x;  // block 600
    float aF = 0.f, aB = 0.f;
    for (int s = 0; s < S_; s++) {
        float w = g_scores[b][s];
        size_t tl = ((size_t)b * S_ + s) * H_;
        aF = fmaf(w, g_fst[tl + j], aF);
        aB = fmaf(w, g_bst[tl + j], aB);
    }
    g_cat[b][j]        = aF;
    g_cat[b][600 + j]  = aB;
    g_cat[b][1200 + j] = g_hs[b][j];
    g_cat[b][1800 + j] = g_hs[b][600 + j];
}

__global__ void k_gated(const float* __restrict__ Wg, const float* __restrict__ bg,
                        const float* __restrict__ Wf, const float* __restrict__ bf) {
    int wid = threadIdx.x >> 5, lane = threadIdx.x & 31;
    int j = blockIdx.x * 8 + wid;
    const float* rg = Wg + (size_t)j * 2400;
    const float* rf = Wf + (size_t)j * 2400;
    for (int b = 0; b < B_; b++) {
        float sg = 0.f, sf = 0.f;
        for (int k = lane; k < 2400; k += 32) {
            float cv = g_cat[b][k];
            sg = fmaf(rg[k], cv, sg);
            sf = fmaf(rf[k], cv, sf);
        }
        #pragma unroll
        for (int off = 16; off; off >>= 1) {
            sg += __shfl_down_sync(0xffffffffu, sg, off);
            sf += __shfl_down_sync(0xffffffffu, sf, off);
        }
        if (lane == 0) {
            float gg = sigmoidf_(sg + bg[j]);
            float ff = tanhf(sf + bf[j]);
            g_gated[b][j] = gg * ff + (1.f - gg) * g_hs[b][j];
        }
    }
}

__global__ void k_attn(float* __restrict__ out) {
    int i = blockIdx.x * blockDim.x + threadIdx.x;   // < T_*300 float4s
    int j4 = i % 300;
    int bs = i / 300;
    int b = bs / S_;
    float4 v = *(const float4*)&g_gated[b][j4 * 4];
    ((float4*)out)[300 + (size_t)bs * 300 + j4] = v;   // out offset 1200 floats
}

// ---------------- launch ----------------
extern "C" void kernel_launch(void* const* d_in, const int* in_sizes, int n_in,
                              void* d_out, int out_size) {
    const float* context = (const float*)d_in[0];
    const int*   tags    = (const int*)  d_in[1];
    const float* bio     = (const float*)d_in[2];
    const float* Wih     = (const float*)d_in[3];
    const float* bih     = (const float*)d_in[4];
    const float* Whh     = (const float*)d_in[5];
    const float* bhh     = (const float*)d_in[6];
    const float* Wlin    = (const float*)d_in[7];
    const float* blin    = (const float*)d_in[8];
    const float* Wg      = (const float*)d_in[9];
    const float* bg      = (const float*)d_in[10];
    const float* Wf      = (const float*)d_in[11];
    const float* bf      = (const float*)d_in[12];
    float* out = (float*)d_out;

    k_init<<<10, 256>>>();
    fused_kernel<<<2 * NCD + MT_TILES * NT_TILES, SCAN_THREADS>>>(
        Whh, bhh, context, tags, bio, Wih, bih);
    k_hs<<<B_, 600>>>(out);
    k_q<<<dim3(150, B_), 256>>>(Wlin, blin);
    k_sdot<<<dim3(S_ / 8, B_), 256>>>();
    k_softmax<<<B_, S_>>>();
    k_ctx<<<B_, 600>>>();
    k_gated<<<150, 256>>>(Wg, bg, Wf, bf);
    k_attn<<<(T_ * 300) / 256, 256>>>(out);
}

// round 14
// speedup vs baseline: 1.1024x; 1.1024x over previous
#include <cuda_runtime.h>
#include <cstdint>
#include <math.h>

#define B_   32
#define S_   384
#define T_   (B_*S_)     // 12288
#define H_   600
#define IN_  303
#define G3_  1800
#define NCD  30          // CTAs per direction (frozen)
#define UPC  20          // hidden units per CTA (1 warp each)
#define SCAN_THREADS 640 // 20 warps

// gemm tiling inside merged kernel
#define TM 128
#define TN 64
#define TK 16
#define MT_TILES (T_ / TM)                 // 96 m-tiles (3 per batch)
#define NT_TILES ((G3_ + TN - 1) / TN)     // 29 n-tiles
#define TILES_PER_BATCH (3 * NT_TILES)     // 87

// ---------------- device scratch (static allocation only) ----------------
__device__ float g_G[(size_t)T_ * G3_];     // input projections, 88.5 MB
__device__ float g_fst[(size_t)T_ * H_];    // forward hidden states
__device__ float g_bst[(size_t)T_ * H_];    // backward hidden states
// self-synchronizing h exchange: (tag<<32)|bits(h), [phase][dir][unit]
__device__ __align__(16) unsigned long long g_hx[2][2][640];
__device__ int   g_done[B_];                // per-batch gemm-tile completion counters
__device__ float g_hs[B_][1200];
__device__ float g_q[B_][1200];
__device__ float g_scores[B_][S_];
__device__ float g_cat[B_][2400];
__device__ float g_gated[B_][1200];

// ---------------- helpers ----------------
__device__ __forceinline__ void cp_async4(void* smem, const void* gmem) {
    uint32_t s = (uint32_t)__cvta_generic_to_shared(smem);
    asm volatile("cp.async.ca.shared.global [%0], [%1], 4;\n" :: "r"(s), "l"(gmem));
}
__device__ __forceinline__ void cp_commit() { asm volatile("cp.async.commit_group;\n"); }
__device__ __forceinline__ void cp_wait3()  { asm volatile("cp.async.wait_group 3;\n"); }

// 16B poll: two adjacent (tag|h) pairs; each aligned 8B half individually atomic
__device__ __forceinline__ void ld_pair2(const unsigned long long* p,
                                         unsigned long long& a, unsigned long long& b) {
    asm volatile("ld.volatile.global.v2.u64 {%0,%1}, [%2];" : "=l"(a), "=l"(b) : "l"(p));
}
__device__ __forceinline__ void st_pair(unsigned long long* p, unsigned long long v) {
    asm volatile("st.relaxed.gpu.global.b64 [%0], %1;" :: "l"(p), "l"(v));
}
__device__ __forceinline__ int ld_acquire_s32(const int* p) {
    int v;
    asm volatile("ld.acquire.gpu.global.s32 %0, [%1];" : "=r"(v) : "l"(p));
    return v;
}
__device__ __forceinline__ void red_release_add(int* p, int v) {
    asm volatile("red.release.gpu.global.add.s32 [%0], %1;" :: "l"(p), "r"(v));
}
__device__ __forceinline__ void ffma2(unsigned long long& d, unsigned long long a,
                                      unsigned long long b, unsigned long long c) {
    asm("fma.rn.f32x2 %0, %1, %2, %3;" : "=l"(d) : "l"(a), "l"(b), "l"(c));
}

__device__ __forceinline__ float fast_tanh(float x) {
    float y;
    asm("tanh.approx.f32 %0, %1;" : "=f"(y) : "f"(x));
    return y;
}
__device__ __forceinline__ float fast_sigmoid(float x) {
    return 0.5f * fast_tanh(0.5f * x) + 0.5f;
}
__device__ __forceinline__ float sigmoidf_(float x) { return 1.f / (1.f + expf(-x)); }

__device__ __forceinline__ int grow_for(int dir, int t) {
    if (dir == 0) return t;
    int b = t / S_, s = t - b * S_;
    return b * S_ + (S_ - 1 - s);
}

// ---------------- init: reset exchange state each launch ----------------
__global__ void k_init() {
    int i = blockIdx.x * blockDim.x + threadIdx.x;
    if (i < 2 * 2 * 640) ((unsigned long long*)g_hx)[i] = 0ull;  // h=0, tag=0
    if (i < B_) g_done[i] = 0;
}

// ============ merged persistent kernel: scan (blocks 0..59) + gemm (60..) ============
__global__ __launch_bounds__(SCAN_THREADS, 1)
void fused_kernel(const float* __restrict__ Whh, const float* __restrict__ bhh,
                  const float* __restrict__ ctx, const int* __restrict__ tags,
                  const float* __restrict__ bio, const float* __restrict__ Wih,
                  const float* __restrict__ bih) {
    const int tid = threadIdx.x;

    if (blockIdx.x >= 2 * NCD) {
        // ---------------- gemm path: one 128x64 tile of G = emb @ Wih.T + bih ----------
        __shared__ float As[TK][TM + 4];
        __shared__ float Bs[TK][TN + 4];
        const int gb = blockIdx.x - 2 * NCD;
        const int mt = gb / NT_TILES;
        const int nt = gb % NT_TILES;
        const int m0 = mt * TM;
        const int n0 = nt * TN;
        const bool act = tid < 256;           // 256 worker threads; all 640 hit barriers
        const int tx = tid & 15, ty = tid >> 4;

        float acc[8][4];
        #pragma unroll
        for (int i = 0; i < 8; i++)
            #pragma unroll
            for (int j = 0; j < 4; j++) acc[i][j] = 0.f;

        for (int k0 = 0; k0 < IN_; k0 += TK) {
            if (act) {
                #pragma unroll
                for (int i = 0; i < 8; i++) {
                    int am = ty + i * 16;
                    int k = k0 + tx;
                    int t = m0 + am;
                    float v = 0.f;
                    if (k < IN_) {
                        if (k < 3) v = bio[tags[t] * 3 + k];
                        else       v = ctx[(size_t)t * 300 + (k - 3)];
                    }
                    As[tx][am] = v;
                }
                #pragma unroll
                for (int i = 0; i < 4; i++) {
                    int bn = ty + i * 16;
                    int j = n0 + bn;
                    int k = k0 + tx;
                    float v = 0.f;
                    if (j < G3_ && k < IN_) v = Wih[(size_t)j * IN_ + k];
                    Bs[tx][bn] = v;
                }
            }
            __syncthreads();
            if (act) {
                #pragma unroll
                for (int kk = 0; kk < TK; kk++) {
                    float a[8], b[4];
                    #pragma unroll
                    for (int i = 0; i < 8; i++) a[i] = As[kk][ty * 8 + i];
                    #pragma unroll
                    for (int j = 0; j < 4; j++) b[j] = Bs[kk][tx * 4 + j];
                    #pragma unroll
                    for (int i = 0; i < 8; i++)
                        #pragma unroll
                        for (int j = 0; j < 4; j++) acc[i][j] = fmaf(a[i], b[j], acc[i][j]);
                }
            }
            __syncthreads();
        }
        if (act) {
            #pragma unroll
            for (int i = 0; i < 8; i++) {
                int t = m0 + ty * 8 + i;
                #pragma unroll
                for (int j = 0; j < 4; j++) {
                    int jj = n0 + tx * 4 + j;
                    if (jj < G3_) g_G[(size_t)t * G3_ + jj] = acc[i][j] + bih[jj];
                }
            }
        }
        __syncthreads();
        if (tid == 0) red_release_add(&g_done[mt / 3], 1);  // publish tile (release)
        return;
    }

    // ---------------- scan path (frozen protocol) -------------------------------------
    const int w    = tid >> 5;
    const int lane = tid & 31;
    const int dir  = blockIdx.x / NCD;
    const int c    = blockIdx.x % NCD;
    const int u0   = c * UPC;
    const int u    = u0 + w;        // hidden unit handled by this warp

    __shared__ __align__(16) float sh_h[648];
    __shared__ float sh_gi[8][64];  // 8 slots so prefetch never writes a live slot

    // W_hh rows packed as f32x2 pairs
    unsigned long long Wr2[10], Wz2[10], Wn2[10];
    #pragma unroll
    for (int m = 0; m < 10; m++) {
        int c0 = 64 * m + 2 * lane;
        float r0 = (c0     < H_) ? Whh[(size_t)u * H_ + c0]              : 0.f;
        float r1 = (c0 + 1 < H_) ? Whh[(size_t)u * H_ + c0 + 1]          : 0.f;
        float z0 = (c0     < H_) ? Whh[(size_t)(600 + u) * H_ + c0]      : 0.f;
        float z1 = (c0 + 1 < H_) ? Whh[(size_t)(600 + u) * H_ + c0 + 1]  : 0.f;
        float n0 = (c0     < H_) ? Whh[(size_t)(1200 + u) * H_ + c0]     : 0.f;
        float n1 = (c0 + 1 < H_) ? Whh[(size_t)(1200 + u) * H_ + c0 + 1] : 0.f;
        Wr2[m] = ((unsigned long long)__float_as_uint(r1) << 32) | __float_as_uint(r0);
        Wz2[m] = ((unsigned long long)__float_as_uint(z1) << 32) | __float_as_uint(z0);
        Wn2[m] = ((unsigned long long)__float_as_uint(n1) << 32) | __float_as_uint(n0);
    }
    const float bhr = bhh[u], bhz = bhh[600 + u], bhn = bhh[1200 + u];

    if (tid < 48) sh_h[600 + tid] = 0.f;   // zero pad cols 600..647 (W pad is 0)

    int rb = -1;   // last batch confirmed ready (prefetch threads only)

    // prologue: prefetch gi for steps 0..3 (batch 0; gate on its readiness)
    for (int tp = 0; tp < 4; tp++) {
        if (tid < 3 * UPC) {
            if (rb < 0) { while (ld_acquire_s32(&g_done[0]) < TILES_PER_BATCH) {} rb = 0; }
            int grow = grow_for(dir, tp);
            int col = (tid / UPC) * 600 + u0 + (tid % UPC);
            cp_async4(&sh_gi[tp][tid], &g_G[(size_t)grow * G3_ + col]);
        }
        cp_commit();
    }

    float* states = dir ? g_bst : g_fst;

    for (int t = 0; t < T_; t++) {
        // 300 threads, 2 units each, one 16B poll. FAST PATH: first sample checked
        // immediately (zero added latency vs R12). SLOW PATH only: spawn a second
        // phase-offset chain (~190cy behind) and alternate — samples land ~RTT/2 apart.
        if (tid < 300) {
            const unsigned long long* p = &g_hx[t & 1][dir][2 * tid];
            const unsigned tt = (unsigned)t;
            unsigned long long a0, a1, r0, r1;
            ld_pair2(p, a0, a1);
            if ((unsigned)(a0 >> 32) == tt && (unsigned)(a1 >> 32) == tt) {
                r0 = a0; r1 = a1;                        // fast path: already published
            } else {
                float dly = (float)(t + 1);
                #pragma unroll
                for (int i = 0; i < 12; i++)             // ~190cy phase offset
                    asm volatile("rcp.approx.f32 %0, %0;" : "+f"(dly));
                unsigned long long b0, b1;
                ld_pair2(p, b0, b1);                     // chain B, offset ~RTT/2
                while (true) {
                    ld_pair2(p, a0, a1);                 // reissue A
                    if ((unsigned)(b0 >> 32) == tt && (unsigned)(b1 >> 32) == tt) { r0 = b0; r1 = b1; break; }
                    ld_pair2(p, b0, b1);                 // reissue B
                    if ((unsigned)(a0 >> 32) == tt && (unsigned)(a1 >> 32) == tt) { r0 = a0; r1 = a1; break; }
                }
            }
            sh_h[2 * tid]     = __uint_as_float((unsigned)r0);
            sh_h[2 * tid + 1] = __uint_as_float((unsigned)r1);
        }
        cp_wait3();          // gi for step t resident
        __syncthreads();

        // 3 dot products of length 600 via packed f32x2 FMA, W in registers
        unsigned long long ar2 = 0ull, az2 = 0ull, an2 = 0ull;
        #pragma unroll
        for (int m = 0; m < 10; m++) {
            unsigned long long h2 = *(const unsigned long long*)&sh_h[64 * m + 2 * lane];
            ffma2(ar2, Wr2[m], h2, ar2);
            ffma2(az2, Wz2[m], h2, az2);
            ffma2(an2, Wn2[m], h2, an2);
        }
        float ar = __uint_as_float((unsigned)ar2) + __uint_as_float((unsigned)(ar2 >> 32));
        float az = __uint_as_float((unsigned)az2) + __uint_as_float((unsigned)(az2 >> 32));
        float an = __uint_as_float((unsigned)an2) + __uint_as_float((unsigned)(an2 >> 32));
        #pragma unroll
        for (int off = 16; off; off >>= 1) {
            ar += __shfl_xor_sync(0xffffffffu, ar, off);
            az += __shfl_xor_sync(0xffffffffu, az, off);
            an += __shfl_xor_sync(0xffffffffu, an, off);
        }

        if (lane == 0) {
            float ir  = sh_gi[t & 7][w];
            float iz  = sh_gi[t & 7][UPC + w];
            float inn = sh_gi[t & 7][2 * UPC + w];
            float r = fast_sigmoid(ir + ar + bhr);
            float z = fast_sigmoid(iz + az + bhz);
            float n = fast_tanh(inn + r * (an + bhn));
            float hprev = sh_h[u];
            float hnew = (1.f - z) * n + z * hprev;
            unsigned long long pv =
                ((unsigned long long)(unsigned)(t + 1) << 32) |
                (unsigned long long)__float_as_uint(hnew);
            st_pair(&g_hx[(t + 1) & 1][dir][u], pv);   // publish first (critical path)
            states[(size_t)t * H_ + u] = hnew;
        }

        // prefetch gi for step t+4; gate on its batch being produced (32 polls total)
        int tp = t + 4;
        if (tp < T_ && tid < 3 * UPC) {
            int bb = tp / S_;
            if (bb != rb) { while (ld_acquire_s32(&g_done[bb]) < TILES_PER_BATCH) {} rb = bb; }
            int grow = grow_for(dir, tp);
            int col = (tid / UPC) * 600 + u0 + (tid % UPC);
            cp_async4(&sh_gi[tp & 7][tid], &g_G[(size_t)grow * G3_ + col]);
        }
        cp_commit();
        __syncthreads();     // confine polling to a short window; protect sh_h rewrite
    }
}

// ---------------- Phase 3 ----------------
__global__ void k_hs(float* __restrict__ out) {
    int b = blockIdx.x, j = threadIdx.x;  // block 600
    size_t tl = ((size_t)b * S_ + (S_ - 1)) * H_;
    g_hs[b][j]       = g_fst[tl + j];
    g_hs[b][600 + j] = g_bst[tl + j];
    if (b == 0) {   // final = concat(h_f, h_b)
        size_t te = ((size_t)T_ - 1) * H_;
        out[j]       = g_fst[te + j];
        out[600 + j] = g_bst[te + j];
    }
}

__global__ void k_q(const float* __restrict__ Wlin, const float* __restrict__ blin) {
    int wid = threadIdx.x >> 5, lane = threadIdx.x & 31;
    int j = blockIdx.x * 8 + wid;
    int b = blockIdx.y;
    const float* row = Wlin + (size_t)j * 1200;
    float s = 0.f;
    for (int k = lane; k < 1200; k += 32) s = fmaf(row[k], g_hs[b][k], s);
    #pragma unroll
    for (int off = 16; off; off >>= 1) s += __shfl_down_sync(0xffffffffu, s, off);
    if (lane == 0) g_q[b][j] = s + blin[j];
}

__global__ void k_sdot() {
    int wid = threadIdx.x >> 5, lane = threadIdx.x & 31;
    int s = blockIdx.x * 8 + wid;
    int b = blockIdx.y;
    size_t tl = ((size_t)b * S_ + s) * H_;
    float acc = 0.f;
    for (int k = lane; k < 600; k += 32) {
        acc = fmaf(g_q[b][k],       g_fst[tl + k], acc);
        acc = fmaf(g_q[b][600 + k], g_bst[tl + k], acc);
    }
    #pragma unroll
    for (int off = 16; off; off >>= 1) acc += __shfl_down_sync(0xffffffffu, acc, off);
    if (lane == 0) g_scores[b][s] = acc;
}

__global__ void k_softmax() {
    int b = blockIdx.x, s = threadIdx.x;   // block 384 = 12 warps
    __shared__ float sm[12];
    __shared__ float bc;
    float v = g_scores[b][s];
    float m = v;
    #pragma unroll
    for (int off = 16; off; off >>= 1) m = fmaxf(m, __shfl_xor_sync(0xffffffffu, m, off));
    if ((s & 31) == 0) sm[s >> 5] = m;
    __syncthreads();
    if (s == 0) {
        float mm = sm[0];
        for (int i = 1; i < 12; i++) mm = fmaxf(mm, sm[i]);
        bc = mm;
    }
    __syncthreads();
    float e = expf(v - bc);
    float t = e;
    #pragma unroll
    for (int off = 16; off; off >>= 1) t += __shfl_xor_sync(0xffffffffu, t, off);
    if ((s & 31) == 0) sm[s >> 5] = t;
    __syncthreads();
    if (s == 0) {
        float ss = 0.f;
        for (int i = 0; i < 12; i++) ss += sm[i];
        bc = ss;
    }
    __syncthreads();
    g_scores[b][s] = e / bc;
}

__global__ void k_ctx() {
    int b = blockIdx.x, j = threadIdx.x;  // block 600
    float aF = 0.f, aB = 0.f;
    for (int s = 0; s < S_; s++) {
        float w = g_scores[b][s];
        size_t tl = ((size_t)b * S_ + s) * H_;
        aF = fmaf(w, g_fst[tl + j], aF);
        aB = fmaf(w, g_bst[tl + j], aB);
    }
    g_cat[b][j]        = aF;
    g_cat[b][600 + j]  = aB;
    g_cat[b][1200 + j] = g_hs[b][j];
    g_cat[b][1800 + j] = g_hs[b][600 + j];
}

__global__ void k_gated(const float* __restrict__ Wg, const float* __restrict__ bg,
                        const float* __restrict__ Wf, const float* __restrict__ bf) {
    int wid = threadIdx.x >> 5, lane = threadIdx.x & 31;
    int j = blockIdx.x * 8 + wid;
    const float* rg = Wg + (size_t)j * 2400;
    const float* rf = Wf + (size_t)j * 2400;
    for (int b = 0; b < B_; b++) {
        float sg = 0.f, sf = 0.f;
        for (int k = lane; k < 2400; k += 32) {
            float cv = g_cat[b][k];
            sg = fmaf(rg[k], cv, sg);
            sf = fmaf(rf[k], cv, sf);
        }
        #pragma unroll
        for (int off = 16; off; off >>= 1) {
            sg += __shfl_down_sync(0xffffffffu, sg, off);
            sf += __shfl_down_sync(0xffffffffu, sf, off);
        }
        if (lane == 0) {
            float gg = sigmoidf_(sg + bg[j]);
            float ff = tanhf(sf + bf[j]);
            g_gated[b][j] = gg * ff + (1.f - gg) * g_hs[b][j];
        }
    }
}

__global__ void k_attn(float* __restrict__ out) {
    int i = blockIdx.x * blockDim.x + threadIdx.x;   // < T_*300 float4s
    int j4 = i % 300;
    int bs = i / 300;
    int b = bs / S_;
    float4 v = *(const float4*)&g_gated[b][j4 * 4];
    ((float4*)out)[300 + (size_t)bs * 300 + j4] = v;   // out offset 1200 floats
}

// ---------------- launch ----------------
extern "C" void kernel_launch(void* const* d_in, const int* in_sizes, int n_in,
                              void* d_out, int out_size) {
    const float* context = (const float*)d_in[0];
    const int*   tags    = (const int*)  d_in[1];
    const float* bio     = (const float*)d_in[2];
    const float* Wih     = (const float*)d_in[3];
    const float* bih     = (const float*)d_in[4];
    const float* Whh     = (const float*)d_in[5];
    const float* bhh     = (const float*)d_in[6];
    const float* Wlin    = (const float*)d_in[7];
    const float* blin    = (const float*)d_in[8];
    const float* Wg      = (const float*)d_in[9];
    const float* bg      = (const float*)d_in[10];
    const float* Wf      = (const float*)d_in[11];
    const float* bf      = (const float*)d_in[12];
    float* out = (float*)d_out;

    k_init<<<10, 256>>>();
    fused_kernel<<<2 * NCD + MT_TILES * NT_TILES, SCAN_THREADS>>>(
        Whh, bhh, context, tags, bio, Wih, bih);
    k_hs<<<B_, 600>>>(out);
    k_q<<<dim3(150, B_), 256>>>(Wlin, blin);
    k_sdot<<<dim3(S_ / 8, B_), 256>>>();
    k_softmax<<<B_, S_>>>();
    k_ctx<<<B_, 600>>>();
    k_gated<<<150, 256>>>(Wg, bg, Wf, bf);
    k_attn<<<(T_ * 300) / 256, 256>>>(out);
}

// round 15
// speedup vs baseline: 1.1768x; 1.0674x over previous
#include <cuda_runtime.h>
#include <cstdint>
#include <math.h>

#define B_   32
#define S_   384
#define T_   (B_*S_)     // 12288
#define H_   600
#define IN_  303
#define G3_  1800
#define NCD  60          // CTAs per direction (16B polls keep sector pressure at proven level)
#define UPC  10          // hidden units per CTA (1 warp each)
#define SCAN_THREADS 320 // 10 warps

// gemm tiling inside merged kernel
#define TM 128
#define TN 64
#define TK 16
#define MT_TILES (T_ / TM)                 // 96 m-tiles (3 per batch)
#define NT_TILES ((G3_ + TN - 1) / TN)     // 29 n-tiles
#define TILES_PER_BATCH (3 * NT_TILES)     // 87

// ---------------- device scratch (static allocation only) ----------------
__device__ float g_G[(size_t)T_ * G3_];     // input projections, 88.5 MB
__device__ float g_fst[(size_t)T_ * H_];    // forward hidden states
__device__ float g_bst[(size_t)T_ * H_];    // backward hidden states
// self-synchronizing h exchange: (tag<<32)|bits(h), [phase][dir][unit]
__device__ __align__(16) unsigned long long g_hx[2][2][640];
__device__ int   g_done[B_];                // per-batch gemm-tile completion counters
__device__ float g_hs[B_][1200];
__device__ float g_q[B_][1200];
__device__ float g_scores[B_][S_];
__device__ float g_cat[B_][2400];
__device__ float g_gated[B_][1200];

// ---------------- helpers ----------------
__device__ __forceinline__ void cp_async4(void* smem, const void* gmem) {
    uint32_t s = (uint32_t)__cvta_generic_to_shared(smem);
    asm volatile("cp.async.ca.shared.global [%0], [%1], 4;\n" :: "r"(s), "l"(gmem));
}
__device__ __forceinline__ void cp_commit() { asm volatile("cp.async.commit_group;\n"); }
__device__ __forceinline__ void cp_wait3()  { asm volatile("cp.async.wait_group 3;\n"); }

// 16B poll: two adjacent (tag|h) pairs; each aligned 8B half individually atomic
__device__ __forceinline__ void ld_pair2(const unsigned long long* p,
                                         unsigned long long& a, unsigned long long& b) {
    asm volatile("ld.volatile.global.v2.u64 {%0,%1}, [%2];" : "=l"(a), "=l"(b) : "l"(p));
}
__device__ __forceinline__ void st_pair(unsigned long long* p, unsigned long long v) {
    asm volatile("st.relaxed.gpu.global.b64 [%0], %1;" :: "l"(p), "l"(v));
}
__device__ __forceinline__ int ld_acquire_s32(const int* p) {
    int v;
    asm volatile("ld.acquire.gpu.global.s32 %0, [%1];" : "=r"(v) : "l"(p));
    return v;
}
__device__ __forceinline__ void red_release_add(int* p, int v) {
    asm volatile("red.release.gpu.global.add.s32 [%0], %1;" :: "l"(p), "r"(v));
}
__device__ __forceinline__ void ffma2(unsigned long long& d, unsigned long long a,
                                      unsigned long long b, unsigned long long c) {
    asm("fma.rn.f32x2 %0, %1, %2, %3;" : "=l"(d) : "l"(a), "l"(b), "l"(c));
}

__device__ __forceinline__ float fast_tanh(float x) {
    float y;
    asm("tanh.approx.f32 %0, %1;" : "=f"(y) : "f"(x));
    return y;
}
__device__ __forceinline__ float fast_sigmoid(float x) {
    return 0.5f * fast_tanh(0.5f * x) + 0.5f;
}
__device__ __forceinline__ float sigmoidf_(float x) { return 1.f / (1.f + expf(-x)); }

__device__ __forceinline__ int grow_for(int dir, int t) {
    if (dir == 0) return t;
    int b = t / S_, s = t - b * S_;
    return b * S_ + (S_ - 1 - s);
}

// ---------------- init: reset exchange state each launch ----------------
__global__ void k_init() {
    int i = blockIdx.x * blockDim.x + threadIdx.x;
    if (i < 2 * 2 * 640) ((unsigned long long*)g_hx)[i] = 0ull;  // h=0, tag=0
    if (i < B_) g_done[i] = 0;
}

// ============ merged persistent kernel: scan (blocks 0..119) + gemm (120..) ==========
__global__ __launch_bounds__(SCAN_THREADS, 1)
void fused_kernel(const float* __restrict__ Whh, const float* __restrict__ bhh,
                  const float* __restrict__ ctx, const int* __restrict__ tags,
                  const float* __restrict__ bio, const float* __restrict__ Wih,
                  const float* __restrict__ bih) {
    const int tid = threadIdx.x;

    if (blockIdx.x >= 2 * NCD) {
        // ---------------- gemm path: one 128x64 tile of G = emb @ Wih.T + bih ----------
        __shared__ float As[TK][TM + 4];
        __shared__ float Bs[TK][TN + 4];
        const int gb = blockIdx.x - 2 * NCD;
        const int mt = gb / NT_TILES;
        const int nt = gb % NT_TILES;
        const int m0 = mt * TM;
        const int n0 = nt * TN;
        const bool act = tid < 256;           // 256 worker threads; all hit barriers
        const int tx = tid & 15, ty = tid >> 4;

        float acc[8][4];
        #pragma unroll
        for (int i = 0; i < 8; i++)
            #pragma unroll
            for (int j = 0; j < 4; j++) acc[i][j] = 0.f;

        for (int k0 = 0; k0 < IN_; k0 += TK) {
            if (act) {
                #pragma unroll
                for (int i = 0; i < 8; i++) {
                    int am = ty + i * 16;
                    int k = k0 + tx;
                    int t = m0 + am;
                    float v = 0.f;
                    if (k < IN_) {
                        if (k < 3) v = bio[tags[t] * 3 + k];
                        else       v = ctx[(size_t)t * 300 + (k - 3)];
                    }
                    As[tx][am] = v;
                }
                #pragma unroll
                for (int i = 0; i < 4; i++) {
                    int bn = ty + i * 16;
                    int j = n0 + bn;
                    int k = k0 + tx;
                    float v = 0.f;
                    if (j < G3_ && k < IN_) v = Wih[(size_t)j * IN_ + k];
                    Bs[tx][bn] = v;
                }
            }
            __syncthreads();
            if (act) {
                #pragma unroll
                for (int kk = 0; kk < TK; kk++) {
                    float a[8], b[4];
                    #pragma unroll
                    for (int i = 0; i < 8; i++) a[i] = As[kk][ty * 8 + i];
                    #pragma unroll
                    for (int j = 0; j < 4; j++) b[j] = Bs[kk][tx * 4 + j];
                    #pragma unroll
                    for (int i = 0; i < 8; i++)
                        #pragma unroll
                        for (int j = 0; j < 4; j++) acc[i][j] = fmaf(a[i], b[j], acc[i][j]);
                }
            }
            __syncthreads();
        }
        if (act) {
            #pragma unroll
            for (int i = 0; i < 8; i++) {
                int t = m0 + ty * 8 + i;
                #pragma unroll
                for (int j = 0; j < 4; j++) {
                    int jj = n0 + tx * 4 + j;
                    if (jj < G3_) g_G[(size_t)t * G3_ + jj] = acc[i][j] + bih[jj];
                }
            }
        }
        __syncthreads();
        if (tid == 0) red_release_add(&g_done[mt / 3], 1);  // publish tile (release)
        return;
    }

    // ---------------- scan path (proven protocol; NCD60 + 16B polls) ------------------
    const int w    = tid >> 5;
    const int lane = tid & 31;
    const int dir  = blockIdx.x / NCD;
    const int c    = blockIdx.x % NCD;
    const int u0   = c * UPC;
    const int u    = u0 + w;        // hidden unit handled by this warp

    __shared__ __align__(16) float sh_h[648];
    __shared__ float sh_gi[8][32];  // 8 slots so prefetch never writes a live slot

    // W_hh rows packed as f32x2 pairs
    unsigned long long Wr2[10], Wz2[10], Wn2[10];
    #pragma unroll
    for (int m = 0; m < 10; m++) {
        int c0 = 64 * m + 2 * lane;
        float r0 = (c0     < H_) ? Whh[(size_t)u * H_ + c0]              : 0.f;
        float r1 = (c0 + 1 < H_) ? Whh[(size_t)u * H_ + c0 + 1]          : 0.f;
        float z0 = (c0     < H_) ? Whh[(size_t)(600 + u) * H_ + c0]      : 0.f;
        float z1 = (c0 + 1 < H_) ? Whh[(size_t)(600 + u) * H_ + c0 + 1]  : 0.f;
        float n0 = (c0     < H_) ? Whh[(size_t)(1200 + u) * H_ + c0]     : 0.f;
        float n1 = (c0 + 1 < H_) ? Whh[(size_t)(1200 + u) * H_ + c0 + 1] : 0.f;
        Wr2[m] = ((unsigned long long)__float_as_uint(r1) << 32) | __float_as_uint(r0);
        Wz2[m] = ((unsigned long long)__float_as_uint(z1) << 32) | __float_as_uint(z0);
        Wn2[m] = ((unsigned long long)__float_as_uint(n1) << 32) | __float_as_uint(n0);
    }
    const float bhr = bhh[u], bhz = bhh[600 + u], bhn = bhh[1200 + u];

    if (tid < 48) sh_h[600 + tid] = 0.f;   // zero pad cols 600..647 (W pad is 0)

    int rb = -1;   // last batch confirmed ready (prefetch threads only)

    // prologue: prefetch gi for steps 0..3 (batch 0; gate on its readiness)
    for (int tp = 0; tp < 4; tp++) {
        if (tid < 3 * UPC) {
            if (rb < 0) { while (ld_acquire_s32(&g_done[0]) < TILES_PER_BATCH) {} rb = 0; }
            int grow = grow_for(dir, tp);
            int col = (tid / UPC) * 600 + u0 + (tid % UPC);
            cp_async4(&sh_gi[tp][tid], &g_G[(size_t)grow * G3_ + col]);
        }
        cp_commit();
    }

    float* states = dir ? g_bst : g_fst;

    for (int t = 0; t < T_; t++) {
        // 300 threads, 2 units each, one 16B volatile poll (proven R12 loop)
        if (tid < 300) {
            const unsigned long long* p = &g_hx[t & 1][dir][2 * tid];
            unsigned long long v0, v1;
            ld_pair2(p, v0, v1);
            while ((unsigned)(v0 >> 32) != (unsigned)t ||
                   (unsigned)(v1 >> 32) != (unsigned)t) ld_pair2(p, v0, v1);
            sh_h[2 * tid]     = __uint_as_float((unsigned)v0);
            sh_h[2 * tid + 1] = __uint_as_float((unsigned)v1);
        }
        cp_wait3();          // gi for step t resident
        __syncthreads();

        // 3 dot products of length 600 via packed f32x2 FMA, W in registers
        unsigned long long ar2 = 0ull, az2 = 0ull, an2 = 0ull;
        #pragma unroll
        for (int m = 0; m < 10; m++) {
            unsigned long long h2 = *(const unsigned long long*)&sh_h[64 * m + 2 * lane];
            ffma2(ar2, Wr2[m], h2, ar2);
            ffma2(az2, Wz2[m], h2, az2);
            ffma2(an2, Wn2[m], h2, an2);
        }
        float ar = __uint_as_float((unsigned)ar2) + __uint_as_float((unsigned)(ar2 >> 32));
        float az = __uint_as_float((unsigned)az2) + __uint_as_float((unsigned)(az2 >> 32));
        float an = __uint_as_float((unsigned)an2) + __uint_as_float((unsigned)(an2 >> 32));
        #pragma unroll
        for (int off = 16; off; off >>= 1) {
            ar += __shfl_xor_sync(0xffffffffu, ar, off);
            az += __shfl_xor_sync(0xffffffffu, az, off);
            an += __shfl_xor_sync(0xffffffffu, an, off);
        }

        if (lane == 0) {
            float ir  = sh_gi[t & 7][w];
            float iz  = sh_gi[t & 7][UPC + w];
            float inn = sh_gi[t & 7][2 * UPC + w];
            float r = fast_sigmoid(ir + ar + bhr);
            float z = fast_sigmoid(iz + az + bhz);
            float n = fast_tanh(inn + r * (an + bhn));
            float hprev = sh_h[u];
            float hnew = (1.f - z) * n + z * hprev;
            unsigned long long pv =
                ((unsigned long long)(unsigned)(t + 1) << 32) |
                (unsigned long long)__float_as_uint(hnew);
            st_pair(&g_hx[(t + 1) & 1][dir][u], pv);   // publish first (critical path)
            states[(size_t)t * H_ + u] = hnew;
        }

        // prefetch gi for step t+4; gate on its batch being produced (32 polls total)
        int tp = t + 4;
        if (tp < T_ && tid < 3 * UPC) {
            int bb = tp / S_;
            if (bb != rb) { while (ld_acquire_s32(&g_done[bb]) < TILES_PER_BATCH) {} rb = bb; }
            int grow = grow_for(dir, tp);
            int col = (tid / UPC) * 600 + u0 + (tid % UPC);
            cp_async4(&sh_gi[tp & 7][tid], &g_G[(size_t)grow * G3_ + col]);
        }
        cp_commit();
        __syncthreads();     // confine polling to a short window; protect sh_h rewrite
    }
}

// ---------------- Phase 3 ----------------
__global__ void k_hs(float* __restrict__ out) {
    int b = blockIdx.x, j = threadIdx.x;  // block 600
    size_t tl = ((size_t)b * S_ + (S_ - 1)) * H_;
    g_hs[b][j]       = g_fst[tl + j];
    g_hs[b][600 + j] = g_bst[tl + j];
    if (b == 0) {   // final = concat(h_f, h_b)
        size_t te = ((size_t)T_ - 1) * H_;
        out[j]       = g_fst[te + j];
        out[600 + j] = g_bst[te + j];
    }
}

__global__ void k_q(const float* __restrict__ Wlin, const float* __restrict__ blin) {
    int wid = threadIdx.x >> 5, lane = threadIdx.x & 31;
    int j = blockIdx.x * 8 + wid;
    int b = blockIdx.y;
    const float* row = Wlin + (size_t)j * 1200;
    float s = 0.f;
    for (int k = lane; k < 1200; k += 32) s = fmaf(row[k], g_hs[b][k], s);
    #pragma unroll
    for (int off = 16; off; off >>= 1) s += __shfl_down_sync(0xffffffffu, s, off);
    if (lane == 0) g_q[b][j] = s + blin[j];
}

__global__ void k_sdot() {
    int wid = threadIdx.x >> 5, lane = threadIdx.x & 31;
    int s = blockIdx.x * 8 + wid;
    int b = blockIdx.y;
    size_t tl = ((size_t)b * S_ + s) * H_;
    float acc = 0.f;
    for (int k = lane; k < 600; k += 32) {
        acc = fmaf(g_q[b][k],       g_fst[tl + k], acc);
        acc = fmaf(g_q[b][600 + k], g_bst[tl + k], acc);
    }
    #pragma unroll
    for (int off = 16; off; off >>= 1) acc += __shfl_down_sync(0xffffffffu, acc, off);
    if (lane == 0) g_scores[b][s] = acc;
}

__global__ void k_softmax() {
    int b = blockIdx.x, s = threadIdx.x;   // block 384 = 12 warps
    __shared__ float sm[12];
    __shared__ float bc;
    float v = g_scores[b][s];
    float m = v;
    #pragma unroll
    for (int off = 16; off; off >>= 1) m = fmaxf(m, __shfl_xor_sync(0xffffffffu, m, off));
    if ((s & 31) == 0) sm[s >> 5] = m;
    __syncthreads();
    if (s == 0) {
        float mm = sm[0];
        for (int i = 1; i < 12; i++) mm = fmaxf(mm, sm[i]);
        bc = mm;
    }
    __syncthreads();
    float e = expf(v - bc);
    float t = e;
    #pragma unroll
    for (int off = 16; off; off >>= 1) t += __shfl_xor_sync(0xffffffffu, t, off);
    if ((s & 31) == 0) sm[s >> 5] = t;
    __syncthreads();
    if (s == 0) {
        float ss = 0.f;
        for (int i = 0; i < 12; i++) ss += sm[i];
        bc = ss;
    }
    __syncthreads();
    g_scores[b][s] = e / bc;
}

__global__ void k_ctx() {
    int b = blockIdx.x, j = threadIdx.x;  // block 600
    float aF = 0.f, aB = 0.f;
    for (int s = 0; s < S_; s++) {
        float w = g_scores[b][s];
        size_t tl = ((size_t)b * S_ + s) * H_;
        aF = fmaf(w, g_fst[tl + j], aF);
        aB = fmaf(w, g_bst[tl + j], aB);
    }
    g_cat[b][j]        = aF;
    g_cat[b][600 + j]  = aB;
    g_cat[b][1200 + j] = g_hs[b][j];
    g_cat[b][1800 + j] = g_hs[b][600 + j];
}

__global__ void k_gated(const float* __restrict__ Wg, const float* __restrict__ bg,
                        const float* __restrict__ Wf, const float* __restrict__ bf) {
    int wid = threadIdx.x >> 5, lane = threadIdx.x & 31;
    int j = blockIdx.x * 8 + wid;
    const float* rg = Wg + (size_t)j * 2400;
    const float* rf = Wf + (size_t)j * 2400;
    for (int b = 0; b < B_; b++) {
        float sg = 0.f, sf = 0.f;
        for (int k = lane; k < 2400; k += 32) {
            float cv = g_cat[b][k];
            sg = fmaf(rg[k], cv, sg);
            sf = fmaf(rf[k], cv, sf);
        }
        #pragma unroll
        for (int off = 16; off; off >>= 1) {
            sg += __shfl_down_sync(0xffffffffu, sg, off);
            sf += __shfl_down_sync(0xffffffffu, sf, off);
        }
        if (lane == 0) {
            float gg = sigmoidf_(sg + bg[j]);
            float ff = tanhf(sf + bf[j]);
            g_gated[b][j] = gg * ff + (1.f - gg) * g_hs[b][j];
        }
    }
}

__global__ void k_attn(float* __restrict__ out) {
    int i = blockIdx.x * blockDim.x + threadIdx.x;   // < T_*300 float4s
    int j4 = i % 300;
    int bs = i / 300;
    int b = bs / S_;
    float4 v = *(const float4*)&g_gated[b][j4 * 4];
    ((float4*)out)[300 + (size_t)bs * 300 + j4] = v;   // out offset 1200 floats
}

// ---------------- launch ----------------
extern "C" void kernel_launch(void* const* d_in, const int* in_sizes, int n_in,
                              void* d_out, int out_size) {
    const float* context = (const float*)d_in[0];
    const int*   tags    = (const int*)  d_in[1];
    const float* bio     = (const float*)d_in[2];
    const float* Wih     = (const float*)d_in[3];
    const float* bih     = (const float*)d_in[4];
    const float* Whh     = (const float*)d_in[5];
    const float* bhh     = (const float*)d_in[6];
    const float* Wlin    = (const float*)d_in[7];
    const float* blin    = (const float*)d_in[8];
    const float* Wg      = (const float*)d_in[9];
    const float* bg      = (const float*)d_in[10];
    const float* Wf      = (const float*)d_in[11];
    const float* bf      = (const float*)d_in[12];
    float* out = (float*)d_out;

    k_init<<<10, 256>>>();
    fused_kernel<<<2 * NCD + MT_TILES * NT_TILES, SCAN_THREADS>>>(
        Whh, bhh, context, tags, bio, Wih, bih);
    k_hs<<<B_, 600>>>(out);
    k_q<<<dim3(150, B_), 256>>>(Wlin, blin);
    k_sdot<<<dim3(S_ / 8, B_), 256>>>();
    k_softmax<<<B_, S_>>>();
    k_ctx<<<B_, 600>>>();
    k_gated<<<150, 256>>>(Wg, bg, Wf, bf);
    k_attn<<<(T_ * 300) / 256, 256>>>(out);
}